// round 3
// baseline (speedup 1.0000x reference)
#include <cuda_runtime.h>
#include <cuda_bf16.h>
#include <cstdint>
#include <math.h>

// ---------------- static device scratch (no cudaMalloc allowed) ----------------
__device__ float g_xg[16384ull * 3072];   // (B*T, 3H) gate pre-activations, row = b*256+t
__device__ float g_wt[1024 * 1024];       // W_in transposed: [d][h]
__device__ float g_wcomb[3072 * 1024];    // W_ih @ W_in : [g][d]
__device__ float g_bcomb[3072];           // W_ih @ b_in + b_ih
__device__ float g_h[2 * 64 * 1024];      // ping-pong hidden state

// ---------------- helpers ----------------
__device__ __forceinline__ void split_bf16(float x, __nv_bfloat16& hi, __nv_bfloat16& lo) {
    hi = __float2bfloat16(x);
    lo = __float2bfloat16(x - __bfloat162float(hi));
}

__device__ __forceinline__ uint32_t ld_pair(const __nv_bfloat16* p) {
    return *reinterpret_cast<const uint32_t*>(p);
}

__device__ __forceinline__ void mma16816(float* c, const uint32_t* a, const uint32_t* b) {
    asm volatile(
        "mma.sync.aligned.m16n8k16.row.col.f32.bf16.bf16.f32 "
        "{%0,%1,%2,%3}, {%4,%5,%6,%7}, {%8,%9}, {%0,%1,%2,%3};\n"
        : "+f"(c[0]), "+f"(c[1]), "+f"(c[2]), "+f"(c[3])
        : "r"(a[0]), "r"(a[1]), "r"(a[2]), "r"(a[3]), "r"(b[0]), "r"(b[1]));
}

// =====================================================================
// Transpose 1024x1024: out[d][h] = in[h][d]
// =====================================================================
__global__ void transpose_k(const float* __restrict__ in, float* __restrict__ out) {
    __shared__ float t[32][33];
    int x = blockIdx.x * 32 + threadIdx.x;
    int y = blockIdx.y * 32 + threadIdx.y;
    #pragma unroll
    for (int i = 0; i < 32; i += 8)
        t[threadIdx.y + i][threadIdx.x] = in[(size_t)(y + i) * 1024 + x];
    __syncthreads();
    int xo = blockIdx.y * 32 + threadIdx.x;
    int yo = blockIdx.x * 32 + threadIdx.y;
    #pragma unroll
    for (int i = 0; i < 32; i += 8)
        out[(size_t)(yo + i) * 1024 + xo] = t[threadIdx.x][threadIdx.y + i];
}

// =====================================================================
// b_comb[g] = b_ih[g] + sum_h W_ih[g,h] * b_in[h]
// =====================================================================
__global__ void bcomb_k(const float* __restrict__ W_ih, const float* __restrict__ b_in,
                        const float* __restrict__ b_ih, float* __restrict__ out) {
    int g = blockIdx.x * blockDim.x + threadIdx.x;
    if (g < 3072) {
        float s = b_ih[g];
        const float* row = W_ih + (size_t)g * 1024;
        for (int h = 0; h < 1024; h++) s += row[h] * b_in[h];
        out[g] = s;
    }
}

// =====================================================================
// copy kernel
// =====================================================================
__global__ void copy_k(const float* __restrict__ s, float* __restrict__ d, int n) {
    int i = blockIdx.x * blockDim.x + threadIdx.x;
    if (i < n) d[i] = s[i];
}

// =====================================================================
// Generic NT GEMM: C[M,N] = A[M,K] @ B[N,K]^T (+ bias[N])
// bf16 hi/lo 3-product split, fp32 accumulate.
// Block tile 128x128, BK=32, 256 threads = 8 warps (4 m-warps x 2 n-warps),
// warp tile 32x64. Requires N%128==0, K%32==0; M guarded.
// =====================================================================
__global__ __launch_bounds__(256, 1)
void gemm3x_k(const float* __restrict__ A, const float* __restrict__ B,
              const float* __restrict__ bias, float* __restrict__ C,
              int M, int N, int K)
{
    __shared__ __nv_bfloat16 sAhi[128][40];
    __shared__ __nv_bfloat16 sAlo[128][40];
    __shared__ __nv_bfloat16 sBhi[128][40];
    __shared__ __nv_bfloat16 sBlo[128][40];

    const int tid = threadIdx.x;
    const int lane = tid & 31;
    const int warp = tid >> 5;
    const int g = lane >> 2;      // group id 0..7
    const int tig = lane & 3;     // thread in group
    const int m0w = (warp >> 1) * 32;
    const int n0w = (warp & 1) * 64;

    const int mBase = blockIdx.y * 128;
    const int nBase = blockIdx.x * 128;

    float acc[2][8][4];
    #pragma unroll
    for (int mt = 0; mt < 2; mt++)
        #pragma unroll
        for (int nt = 0; nt < 8; nt++)
            #pragma unroll
            for (int i = 0; i < 4; i++) acc[mt][nt][i] = 0.f;

    const int nKT = K >> 5;
    for (int kt = 0; kt < nKT; kt++) {
        const int k0 = kt << 5;
        __syncthreads();
        // stage A tile (128x32) and B tile (128x32): 1024 float4 each
        #pragma unroll
        for (int it = 0; it < 4; it++) {
            int id = tid + it * 256;
            int r = id >> 3;
            int kq = (id & 7) << 2;
            int gr = mBase + r;
            float4 v;
            if (gr < M) v = *reinterpret_cast<const float4*>(A + (size_t)gr * K + k0 + kq);
            else        v = make_float4(0.f, 0.f, 0.f, 0.f);
            __nv_bfloat16 h, l;
            split_bf16(v.x, h, l); sAhi[r][kq + 0] = h; sAlo[r][kq + 0] = l;
            split_bf16(v.y, h, l); sAhi[r][kq + 1] = h; sAlo[r][kq + 1] = l;
            split_bf16(v.z, h, l); sAhi[r][kq + 2] = h; sAlo[r][kq + 2] = l;
            split_bf16(v.w, h, l); sAhi[r][kq + 3] = h; sAlo[r][kq + 3] = l;
        }
        #pragma unroll
        for (int it = 0; it < 4; it++) {
            int id = tid + it * 256;
            int r = id >> 3;
            int kq = (id & 7) << 2;
            float4 v = *reinterpret_cast<const float4*>(B + (size_t)(nBase + r) * K + k0 + kq);
            __nv_bfloat16 h, l;
            split_bf16(v.x, h, l); sBhi[r][kq + 0] = h; sBlo[r][kq + 0] = l;
            split_bf16(v.y, h, l); sBhi[r][kq + 1] = h; sBlo[r][kq + 1] = l;
            split_bf16(v.z, h, l); sBhi[r][kq + 2] = h; sBlo[r][kq + 2] = l;
            split_bf16(v.w, h, l); sBhi[r][kq + 3] = h; sBlo[r][kq + 3] = l;
        }
        __syncthreads();

        #pragma unroll
        for (int kk = 0; kk < 32; kk += 16) {
            uint32_t Ah[2][4], Al[2][4], Bh[8][2], Bl[8][2];
            #pragma unroll
            for (int mt = 0; mt < 2; mt++) {
                int r0 = m0w + 16 * mt;
                Ah[mt][0] = ld_pair(&sAhi[r0 + g][kk + 2 * tig]);
                Ah[mt][1] = ld_pair(&sAhi[r0 + g + 8][kk + 2 * tig]);
                Ah[mt][2] = ld_pair(&sAhi[r0 + g][kk + 2 * tig + 8]);
                Ah[mt][3] = ld_pair(&sAhi[r0 + g + 8][kk + 2 * tig + 8]);
                Al[mt][0] = ld_pair(&sAlo[r0 + g][kk + 2 * tig]);
                Al[mt][1] = ld_pair(&sAlo[r0 + g + 8][kk + 2 * tig]);
                Al[mt][2] = ld_pair(&sAlo[r0 + g][kk + 2 * tig + 8]);
                Al[mt][3] = ld_pair(&sAlo[r0 + g + 8][kk + 2 * tig + 8]);
            }
            #pragma unroll
            for (int nt = 0; nt < 8; nt++) {
                int r0 = n0w + 8 * nt + g;
                Bh[nt][0] = ld_pair(&sBhi[r0][kk + 2 * tig]);
                Bh[nt][1] = ld_pair(&sBhi[r0][kk + 2 * tig + 8]);
                Bl[nt][0] = ld_pair(&sBlo[r0][kk + 2 * tig]);
                Bl[nt][1] = ld_pair(&sBlo[r0][kk + 2 * tig + 8]);
            }
            #pragma unroll
            for (int mt = 0; mt < 2; mt++)
                #pragma unroll
                for (int nt = 0; nt < 8; nt++) {
                    mma16816(acc[mt][nt], Ah[mt], Bh[nt]);
                    mma16816(acc[mt][nt], Ah[mt], Bl[nt]);
                    mma16816(acc[mt][nt], Al[mt], Bh[nt]);
                }
        }
    }

    // epilogue
    #pragma unroll
    for (int mt = 0; mt < 2; mt++) {
        #pragma unroll
        for (int nt = 0; nt < 8; nt++) {
            int col = nBase + n0w + 8 * nt + 2 * tig;
            float b0 = bias ? bias[col] : 0.f;
            float b1 = bias ? bias[col + 1] : 0.f;
            int r0 = mBase + m0w + 16 * mt + g;
            if (r0 < M) {
                C[(size_t)r0 * N + col]     = acc[mt][nt][0] + b0;
                C[(size_t)r0 * N + col + 1] = acc[mt][nt][1] + b1;
            }
            if (r0 + 8 < M) {
                C[(size_t)(r0 + 8) * N + col]     = acc[mt][nt][2] + b0;
                C[(size_t)(r0 + 8) * N + col + 1] = acc[mt][nt][3] + b1;
            }
        }
    }
}

// =====================================================================
// GRU step kernel. grid = 64 blocks, 256 threads (8 warps).
// Block bx owns 16 hidden units j0=16*bx..+15 -> 48 W_hh rows (r,z,n slices).
// Computes hg = h @ W_hh^T for those rows (M=64, N=48, K=1024), then
// applies the gate nonlinearity and writes h_new for its 16 units.
// =====================================================================
__global__ __launch_bounds__(256, 1)
void gru_step_k(const float* __restrict__ xg, const float* __restrict__ W_hh,
                const float* __restrict__ b_hh, const float* __restrict__ hsrc,
                float* __restrict__ hdst, int t)
{
    __shared__ __nv_bfloat16 sAhi[64][40];
    __shared__ __nv_bfloat16 sAlo[64][40];
    __shared__ __nv_bfloat16 sBhi[48][40];
    __shared__ __nv_bfloat16 sBlo[48][40];
    __shared__ float shg[64][49];

    const int tid = threadIdx.x;
    const int lane = tid & 31;
    const int warp = tid >> 5;
    const int g = lane >> 2;
    const int tig = lane & 3;
    const int m0w = (warp >> 1) * 16;   // 4 m-warps
    const int n0w = (warp & 1) * 24;    // 2 n-warps, 3 n8-tiles each
    const int j0 = blockIdx.x * 16;

    float acc[3][4];
    #pragma unroll
    for (int nt = 0; nt < 3; nt++)
        #pragma unroll
        for (int i = 0; i < 4; i++) acc[nt][i] = 0.f;

    for (int kt = 0; kt < 32; kt++) {
        const int k0 = kt << 5;
        __syncthreads();
        // stage A = h tile (64x32): 512 float4
        #pragma unroll
        for (int it = 0; it < 2; it++) {
            int id = tid + it * 256;
            int r = id >> 3;
            int kq = (id & 7) << 2;
            float4 v = *reinterpret_cast<const float4*>(hsrc + (size_t)r * 1024 + k0 + kq);
            __nv_bfloat16 h, l;
            split_bf16(v.x, h, l); sAhi[r][kq + 0] = h; sAlo[r][kq + 0] = l;
            split_bf16(v.y, h, l); sAhi[r][kq + 1] = h; sAlo[r][kq + 1] = l;
            split_bf16(v.z, h, l); sAhi[r][kq + 2] = h; sAlo[r][kq + 2] = l;
            split_bf16(v.w, h, l); sAhi[r][kq + 3] = h; sAlo[r][kq + 3] = l;
        }
        // stage B = W_hh slice (48x32): 384 float4  (FIXED: 2 guarded passes)
        #pragma unroll
        for (int it = 0; it < 2; it++) {
            int id = tid + it * 256;
            if (id < 384) {
                int r = id >> 3;               // local row 0..47
                int kq = (id & 7) << 2;
                int grow = (r >> 4) * 1024 + j0 + (r & 15);
                float4 v = *reinterpret_cast<const float4*>(W_hh + (size_t)grow * 1024 + k0 + kq);
                __nv_bfloat16 h, l;
                split_bf16(v.x, h, l); sBhi[r][kq + 0] = h; sBlo[r][kq + 0] = l;
                split_bf16(v.y, h, l); sBhi[r][kq + 1] = h; sBlo[r][kq + 1] = l;
                split_bf16(v.z, h, l); sBhi[r][kq + 2] = h; sBlo[r][kq + 2] = l;
                split_bf16(v.w, h, l); sBhi[r][kq + 3] = h; sBlo[r][kq + 3] = l;
            }
        }
        __syncthreads();

        #pragma unroll
        for (int kk = 0; kk < 32; kk += 16) {
            uint32_t Ah[4], Al[4], Bh[3][2], Bl[3][2];
            Ah[0] = ld_pair(&sAhi[m0w + g][kk + 2 * tig]);
            Ah[1] = ld_pair(&sAhi[m0w + g + 8][kk + 2 * tig]);
            Ah[2] = ld_pair(&sAhi[m0w + g][kk + 2 * tig + 8]);
            Ah[3] = ld_pair(&sAhi[m0w + g + 8][kk + 2 * tig + 8]);
            Al[0] = ld_pair(&sAlo[m0w + g][kk + 2 * tig]);
            Al[1] = ld_pair(&sAlo[m0w + g + 8][kk + 2 * tig]);
            Al[2] = ld_pair(&sAlo[m0w + g][kk + 2 * tig + 8]);
            Al[3] = ld_pair(&sAlo[m0w + g + 8][kk + 2 * tig + 8]);
            #pragma unroll
            for (int nt = 0; nt < 3; nt++) {
                int r0 = n0w + 8 * nt + g;
                Bh[nt][0] = ld_pair(&sBhi[r0][kk + 2 * tig]);
                Bh[nt][1] = ld_pair(&sBhi[r0][kk + 2 * tig + 8]);
                Bl[nt][0] = ld_pair(&sBlo[r0][kk + 2 * tig]);
                Bl[nt][1] = ld_pair(&sBlo[r0][kk + 2 * tig + 8]);
            }
            #pragma unroll
            for (int nt = 0; nt < 3; nt++) {
                mma16816(acc[nt], Ah, Bh[nt]);
                mma16816(acc[nt], Ah, Bl[nt]);
                mma16816(acc[nt], Al, Bh[nt]);
            }
        }
    }

    // write hg tile to smem
    #pragma unroll
    for (int nt = 0; nt < 3; nt++) {
        int col = n0w + 8 * nt + 2 * tig;
        shg[m0w + g][col]         = acc[nt][0];
        shg[m0w + g][col + 1]     = acc[nt][1];
        shg[m0w + g + 8][col]     = acc[nt][2];
        shg[m0w + g + 8][col + 1] = acc[nt][3];
    }
    __syncthreads();

    // gate nonlinearity + h update: 64 batch x 16 units = 1024 elems
    #pragma unroll
    for (int u = tid; u < 1024; u += 256) {
        int b_ = u >> 4;
        int uu = u & 15;
        size_t xrow = (size_t)(b_ * 256 + t) * 3072;
        float xr = xg[xrow + j0 + uu];
        float xz = xg[xrow + 1024 + j0 + uu];
        float xn = xg[xrow + 2048 + j0 + uu];
        float hr = shg[b_][uu]      + b_hh[j0 + uu];
        float hz = shg[b_][16 + uu] + b_hh[1024 + j0 + uu];
        float hn = shg[b_][32 + uu] + b_hh[2048 + j0 + uu];
        float r = 1.f / (1.f + expf(-(xr + hr)));
        float z = 1.f / (1.f + expf(-(xz + hz)));
        float n = tanhf(xn + r * hn);
        float ho = hsrc[(size_t)b_ * 1024 + j0 + uu];
        hdst[(size_t)b_ * 1024 + j0 + uu] = (1.f - z) * n + z * ho;
    }
}

// =====================================================================
// launch
// =====================================================================
extern "C" void kernel_launch(void* const* d_in, const int* in_sizes, int n_in,
                              void* d_out, int out_size)
{
    const float* inp    = (const float*)d_in[0];  // (64,256,1024)
    const float* hidden = (const float*)d_in[1];  // (1,64,1024)
    const float* W_in   = (const float*)d_in[2];  // (1024,1024)
    const float* b_in   = (const float*)d_in[3];  // (1024)
    const float* W_ih   = (const float*)d_in[4];  // (3072,1024)
    const float* b_ih   = (const float*)d_in[5];  // (3072)
    const float* W_hh   = (const float*)d_in[6];  // (3072,1024)
    const float* b_hh   = (const float*)d_in[7];  // (3072)
    const float* W_out  = (const float*)d_in[8];  // (1024,1024)
    const float* b_out  = (const float*)d_in[9];  // (1024)
    float* out = (float*)d_out;

    float* xg    = g_xg;
    float* wt    = g_wt;
    float* wcomb = g_wcomb;
    float* bcomb = g_bcomb;
    float* hbuf  = g_h;

    // W_in^T
    transpose_k<<<dim3(32, 32), dim3(32, 8)>>>(W_in, wt);
    // b_comb
    bcomb_k<<<12, 256>>>(W_ih, b_in, b_ih, bcomb);
    // W_comb = W_ih @ W_in  (M=3072, N=1024, K=1024)
    gemm3x_k<<<dim3(8, 24), 256>>>(W_ih, wt, nullptr, wcomb, 3072, 1024, 1024);
    // x_gates = inp @ W_comb^T + b_comb  (M=16384, N=3072, K=1024)
    gemm3x_k<<<dim3(24, 128), 256>>>(inp, wcomb, bcomb, xg, 16384, 3072, 1024);
    // h0
    copy_k<<<256, 256>>>(hidden, hbuf, 65536);
    // recurrence
    for (int t = 0; t < 256; t++) {
        const float* hs = hbuf + (size_t)(t & 1) * 65536;
        float* hd = hbuf + (size_t)((t + 1) & 1) * 65536;
        gru_step_k<<<64, 256>>>(xg, W_hh, b_hh, hs, hd, t);
    }
    // final h lives in buffer 0 after 256 steps
    // out_last = h_T @ W_out^T + b_out  (M=64, N=1024, K=1024)
    gemm3x_k<<<dim3(8, 1), 256>>>(hbuf, W_out, b_out, out, 64, 1024, 1024);
    // hidden_out = h_T
    copy_k<<<256, 256>>>(hbuf, out + 65536, 65536);
}

// round 4
// speedup vs baseline: 1.1838x; 1.1838x over previous
#include <cuda_runtime.h>
#include <cuda_bf16.h>
#include <cstdint>
#include <math.h>

// ---------------- static device scratch (no cudaMalloc allowed) ----------------
__device__ float g_xg[16384ull * 3072];   // (B*T, 3H) gate pre-activations, row = b*256+t
__device__ float g_wt[1024 * 1024];       // W_in transposed: [d][h]
__device__ float g_wcomb[3072 * 1024];    // W_ih @ W_in : [g][d]
__device__ float g_bcomb[3072];           // W_ih @ b_in + b_ih
__device__ float g_h[2 * 64 * 1024];      // ping-pong hidden state
__device__ unsigned g_cnt = 0;            // grid barrier arrive counter
__device__ unsigned g_gen = 0;            // grid barrier generation

// ---------------- helpers ----------------
__device__ __forceinline__ void split_bf16(float x, __nv_bfloat16& hi, __nv_bfloat16& lo) {
    hi = __float2bfloat16(x);
    lo = __float2bfloat16(x - __bfloat162float(hi));
}

__device__ __forceinline__ uint32_t ld_pair(const __nv_bfloat16* p) {
    return *reinterpret_cast<const uint32_t*>(p);
}

__device__ __forceinline__ void mma16816(float* c, const uint32_t* a, const uint32_t* b) {
    asm volatile(
        "mma.sync.aligned.m16n8k16.row.col.f32.bf16.bf16.f32 "
        "{%0,%1,%2,%3}, {%4,%5,%6,%7}, {%8,%9}, {%0,%1,%2,%3};\n"
        : "+f"(c[0]), "+f"(c[1]), "+f"(c[2]), "+f"(c[3])
        : "r"(a[0]), "r"(a[1]), "r"(a[2]), "r"(a[3]), "r"(b[0]), "r"(b[1]));
}

// =====================================================================
// Transpose 1024x1024: out[d][h] = in[h][d]
// =====================================================================
__global__ void transpose_k(const float* __restrict__ in, float* __restrict__ out) {
    __shared__ float t[32][33];
    int x = blockIdx.x * 32 + threadIdx.x;
    int y = blockIdx.y * 32 + threadIdx.y;
    #pragma unroll
    for (int i = 0; i < 32; i += 8)
        t[threadIdx.y + i][threadIdx.x] = in[(size_t)(y + i) * 1024 + x];
    __syncthreads();
    int xo = blockIdx.y * 32 + threadIdx.x;
    int yo = blockIdx.x * 32 + threadIdx.y;
    #pragma unroll
    for (int i = 0; i < 32; i += 8)
        out[(size_t)(yo + i) * 1024 + xo] = t[threadIdx.x][threadIdx.y + i];
}

// =====================================================================
// b_comb[g] = b_ih[g] + sum_h W_ih[g,h] * b_in[h]
// =====================================================================
__global__ void bcomb_k(const float* __restrict__ W_ih, const float* __restrict__ b_in,
                        const float* __restrict__ b_ih, float* __restrict__ out) {
    int g = blockIdx.x * blockDim.x + threadIdx.x;
    if (g < 3072) {
        float s = b_ih[g];
        const float* row = W_ih + (size_t)g * 1024;
        for (int h = 0; h < 1024; h++) s += row[h] * b_in[h];
        out[g] = s;
    }
}

__global__ void copy_k(const float* __restrict__ s, float* __restrict__ d, int n) {
    int i = blockIdx.x * blockDim.x + threadIdx.x;
    if (i < n) d[i] = s[i];
}

// =====================================================================
// Generic NT GEMM: C[M,N] = A[M,K] @ B[N,K]^T (+ bias[N])
// bf16 hi/lo 3-product split, fp32 accumulate.
// Block tile 128x128, BK=32, 256 threads = 8 warps (4 m-warps x 2 n-warps).
// Dynamic smem, DOUBLE-BUFFERED, register prefetch, 1 sync per k-tile.
// Requires N%128==0, K%32==0; M guarded.
// =====================================================================
#define GTILE 5120   // 128*40 elems per array
#define GEMM_SMEM (2 * 4 * GTILE * 2)   // bytes = 81920

__global__ __launch_bounds__(256, 1)
void gemm3x_k(const float* __restrict__ A, const float* __restrict__ B,
              const float* __restrict__ bias, float* __restrict__ C,
              int M, int N, int K)
{
    extern __shared__ __nv_bfloat16 gsm[];

    const int tid = threadIdx.x;
    const int lane = tid & 31;
    const int warp = tid >> 5;
    const int g = lane >> 2;      // group id 0..7
    const int tig = lane & 3;     // thread in group
    const int m0w = (warp >> 1) * 32;
    const int n0w = (warp & 1) * 64;

    const int mBase = blockIdx.y * 128;
    const int nBase = blockIdx.x * 128;

    float acc[2][8][4];
    #pragma unroll
    for (int mt = 0; mt < 2; mt++)
        #pragma unroll
        for (int nt = 0; nt < 8; nt++)
            #pragma unroll
            for (int i = 0; i < 4; i++) acc[mt][nt][i] = 0.f;

    const int nKT = K >> 5;
    float4 pa[4], pb[4];

    // prologue: prefetch tile 0 into regs
    #pragma unroll
    for (int it = 0; it < 4; it++) {
        int id = tid + it * 256;
        int r = id >> 3;
        int kq = (id & 7) << 2;
        int gr = mBase + r;
        pa[it] = (gr < M) ? *reinterpret_cast<const float4*>(A + (size_t)gr * K + kq)
                          : make_float4(0.f, 0.f, 0.f, 0.f);
        pb[it] = *reinterpret_cast<const float4*>(B + (size_t)(nBase + r) * K + kq);
    }

    for (int kt = 0; kt < nKT; kt++) {
        __nv_bfloat16* base = gsm + (size_t)(kt & 1) * (4 * GTILE);
        __nv_bfloat16* sAhi = base;
        __nv_bfloat16* sAlo = base + GTILE;
        __nv_bfloat16* sBhi = base + 2 * GTILE;
        __nv_bfloat16* sBlo = base + 3 * GTILE;

        // store prefetched regs -> smem (split)
        #pragma unroll
        for (int it = 0; it < 4; it++) {
            int id = tid + it * 256;
            int r = id >> 3;
            int kq = (id & 7) << 2;
            __nv_bfloat16 h, l;
            split_bf16(pa[it].x, h, l); sAhi[r * 40 + kq + 0] = h; sAlo[r * 40 + kq + 0] = l;
            split_bf16(pa[it].y, h, l); sAhi[r * 40 + kq + 1] = h; sAlo[r * 40 + kq + 1] = l;
            split_bf16(pa[it].z, h, l); sAhi[r * 40 + kq + 2] = h; sAlo[r * 40 + kq + 2] = l;
            split_bf16(pa[it].w, h, l); sAhi[r * 40 + kq + 3] = h; sAlo[r * 40 + kq + 3] = l;
            split_bf16(pb[it].x, h, l); sBhi[r * 40 + kq + 0] = h; sBlo[r * 40 + kq + 0] = l;
            split_bf16(pb[it].y, h, l); sBhi[r * 40 + kq + 1] = h; sBlo[r * 40 + kq + 1] = l;
            split_bf16(pb[it].z, h, l); sBhi[r * 40 + kq + 2] = h; sBlo[r * 40 + kq + 2] = l;
            split_bf16(pb[it].w, h, l); sBhi[r * 40 + kq + 3] = h; sBlo[r * 40 + kq + 3] = l;
        }
        __syncthreads();

        // prefetch next tile under this tile's MMAs
        if (kt + 1 < nKT) {
            int k0 = (kt + 1) << 5;
            #pragma unroll
            for (int it = 0; it < 4; it++) {
                int id = tid + it * 256;
                int r = id >> 3;
                int kq = (id & 7) << 2;
                int gr = mBase + r;
                pa[it] = (gr < M) ? *reinterpret_cast<const float4*>(A + (size_t)gr * K + k0 + kq)
                                  : make_float4(0.f, 0.f, 0.f, 0.f);
                pb[it] = *reinterpret_cast<const float4*>(B + (size_t)(nBase + r) * K + k0 + kq);
            }
        }

        #pragma unroll
        for (int kk = 0; kk < 32; kk += 16) {
            uint32_t Ah[2][4], Al[2][4], Bh[8][2], Bl[8][2];
            #pragma unroll
            for (int mt = 0; mt < 2; mt++) {
                int r0 = m0w + 16 * mt;
                Ah[mt][0] = ld_pair(&sAhi[(r0 + g) * 40 + kk + 2 * tig]);
                Ah[mt][1] = ld_pair(&sAhi[(r0 + g + 8) * 40 + kk + 2 * tig]);
                Ah[mt][2] = ld_pair(&sAhi[(r0 + g) * 40 + kk + 2 * tig + 8]);
                Ah[mt][3] = ld_pair(&sAhi[(r0 + g + 8) * 40 + kk + 2 * tig + 8]);
                Al[mt][0] = ld_pair(&sAlo[(r0 + g) * 40 + kk + 2 * tig]);
                Al[mt][1] = ld_pair(&sAlo[(r0 + g + 8) * 40 + kk + 2 * tig]);
                Al[mt][2] = ld_pair(&sAlo[(r0 + g) * 40 + kk + 2 * tig + 8]);
                Al[mt][3] = ld_pair(&sAlo[(r0 + g + 8) * 40 + kk + 2 * tig + 8]);
            }
            #pragma unroll
            for (int nt = 0; nt < 8; nt++) {
                int r0 = n0w + 8 * nt + g;
                Bh[nt][0] = ld_pair(&sBhi[r0 * 40 + kk + 2 * tig]);
                Bh[nt][1] = ld_pair(&sBhi[r0 * 40 + kk + 2 * tig + 8]);
                Bl[nt][0] = ld_pair(&sBlo[r0 * 40 + kk + 2 * tig]);
                Bl[nt][1] = ld_pair(&sBlo[r0 * 40 + kk + 2 * tig + 8]);
            }
            #pragma unroll
            for (int mt = 0; mt < 2; mt++)
                #pragma unroll
                for (int nt = 0; nt < 8; nt++) {
                    mma16816(acc[mt][nt], Ah[mt], Bh[nt]);
                    mma16816(acc[mt][nt], Ah[mt], Bl[nt]);
                    mma16816(acc[mt][nt], Al[mt], Bh[nt]);
                }
        }
        // no trailing sync: next iter writes the OTHER buffer, whose readers
        // all passed this iter's __syncthreads before issuing those reads.
    }

    // epilogue
    #pragma unroll
    for (int mt = 0; mt < 2; mt++) {
        #pragma unroll
        for (int nt = 0; nt < 8; nt++) {
            int col = nBase + n0w + 8 * nt + 2 * tig;
            float b0 = bias ? bias[col] : 0.f;
            float b1 = bias ? bias[col + 1] : 0.f;
            int r0 = mBase + m0w + 16 * mt + g;
            if (r0 < M) {
                C[(size_t)r0 * N + col]     = acc[mt][nt][0] + b0;
                C[(size_t)r0 * N + col + 1] = acc[mt][nt][1] + b1;
            }
            if (r0 + 8 < M) {
                C[(size_t)(r0 + 8) * N + col]     = acc[mt][nt][2] + b0;
                C[(size_t)(r0 + 8) * N + col + 1] = acc[mt][nt][3] + b1;
            }
        }
    }
}

// =====================================================================
// Persistent GRU recurrence kernel.
// grid = 64 blocks x 256 threads, ALL co-resident (1 CTA/SM, 64 <= 148 SMs).
// Block bx owns 16 hidden units -> 48 W_hh rows, which it stages into smem
// as bf16 hi/lo ONCE (192KB). Then 256 steps, each: stage h k-tiles
// (double-buffered, reg-prefetch), 3x-split MMA, fused gates, global barrier.
// =====================================================================
#define WSTR 1032                       // W smem row stride (bank conflict-free: {4g+tig})
#define ASTR 40                         // A smem row stride
#define GRU_SMEM ((2 * 48 * WSTR + 2 * 2 * 64 * ASTR) * 2)   // 218624 bytes
#define NBLK 64

__device__ __forceinline__ void gridbar64() {
    __syncthreads();
    if (threadIdx.x == 0) {
        __threadfence();                       // release (cumulative): publish block's h writes
        unsigned gen = atomicAdd(&g_gen, 0u);  // read generation BEFORE arriving
        if (atomicAdd(&g_cnt, 1u) == NBLK - 1u) {
            atomicExch(&g_cnt, 0u);
            __threadfence();
            atomicAdd(&g_gen, 1u);
        } else {
            while (atomicAdd(&g_gen, 0u) == gen) { }
        }
        __threadfence();                       // acquire + L1D invalidate (CCTL.IVALL)
    }
    __syncthreads();
}

__global__ __launch_bounds__(256, 1)
void gru_persist_k(const float* __restrict__ xg, const float* __restrict__ W_hh,
                   const float* __restrict__ b_hh, const float* __restrict__ hidden,
                   float* __restrict__ hbuf)
{
    extern __shared__ __nv_bfloat16 dsm[];
    __nv_bfloat16* sWhi = dsm;                       // [48][WSTR]
    __nv_bfloat16* sWlo = dsm + 48 * WSTR;
    __nv_bfloat16* sAb  = dsm + 2 * 48 * WSTR;       // [2 buf][hi|lo][64][ASTR]
    float* shg = reinterpret_cast<float*>(sAb);      // [64][49] (reuses A buffers)
    __shared__ float sbh[48];

    const int tid = threadIdx.x;
    const int lane = tid & 31;
    const int warp = tid >> 5;
    const int g = lane >> 2;
    const int tig = lane & 3;
    const int m0w = (warp >> 1) * 16;   // 4 m-warps (batch rows)
    const int n0w = (warp & 1) * 24;    // 2 n-warps, 3 n8-tiles each
    const int j0 = blockIdx.x * 16;

    // ---- stage W_hh slice (48 rows x 1024) into smem, hi/lo ----
    for (int idx = tid; idx < 48 * 256; idx += 256) {
        int r = idx >> 8;                 // 0..47
        int c4 = (idx & 255) << 2;        // 0..1020
        int grow = (r >> 4) * 1024 + j0 + (r & 15);
        float4 v = *reinterpret_cast<const float4*>(W_hh + (size_t)grow * 1024 + c4);
        __nv_bfloat16 h, l;
        split_bf16(v.x, h, l); sWhi[r * WSTR + c4 + 0] = h; sWlo[r * WSTR + c4 + 0] = l;
        split_bf16(v.y, h, l); sWhi[r * WSTR + c4 + 1] = h; sWlo[r * WSTR + c4 + 1] = l;
        split_bf16(v.z, h, l); sWhi[r * WSTR + c4 + 2] = h; sWlo[r * WSTR + c4 + 2] = l;
        split_bf16(v.w, h, l); sWhi[r * WSTR + c4 + 3] = h; sWlo[r * WSTR + c4 + 3] = l;
    }
    if (tid < 48) sbh[tid] = b_hh[(tid >> 4) * 1024 + j0 + (tid & 15)];
    __syncthreads();

    const int b_  = tid >> 2;             // epilogue: batch row
    const int uu0 = (tid & 3) << 2;       // epilogue: first of 4 units
    const int ar0 = tid >> 3;             // staging row (0..31), +32 for 2nd
    const int akq = (tid & 7) << 2;       // staging col quad

    for (int t = 0; t < 256; t++) {
        const float* hsrc = (t == 0) ? hidden : (hbuf + (size_t)(t & 1) * 65536);
        float* hdst = hbuf + (size_t)((t + 1) & 1) * 65536;

        // prefetch epilogue operands (independent of MMA chain)
        const float* xrow = xg + (size_t)(b_ * 256 + t) * 3072 + j0 + uu0;
        float4 xr4 = *reinterpret_cast<const float4*>(xrow);
        float4 xz4 = *reinterpret_cast<const float4*>(xrow + 1024);
        float4 xn4 = *reinterpret_cast<const float4*>(xrow + 2048);
        float4 ho4 = *reinterpret_cast<const float4*>(hsrc + (size_t)b_ * 1024 + j0 + uu0);

        float acc[3][4];
        #pragma unroll
        for (int nt = 0; nt < 3; nt++)
            #pragma unroll
            for (int i = 0; i < 4; i++) acc[nt][i] = 0.f;

        // prologue: prefetch h tile 0
        float4 pv0 = *reinterpret_cast<const float4*>(hsrc + (size_t)ar0 * 1024 + akq);
        float4 pv1 = *reinterpret_cast<const float4*>(hsrc + (size_t)(ar0 + 32) * 1024 + akq);

        for (int kt = 0; kt < 32; kt++) {
            __nv_bfloat16* sAhi = sAb + (size_t)(kt & 1) * (2 * 64 * ASTR);
            __nv_bfloat16* sAlo = sAhi + 64 * ASTR;

            {
                __nv_bfloat16 h, l;
                split_bf16(pv0.x, h, l); sAhi[ar0 * ASTR + akq + 0] = h; sAlo[ar0 * ASTR + akq + 0] = l;
                split_bf16(pv0.y, h, l); sAhi[ar0 * ASTR + akq + 1] = h; sAlo[ar0 * ASTR + akq + 1] = l;
                split_bf16(pv0.z, h, l); sAhi[ar0 * ASTR + akq + 2] = h; sAlo[ar0 * ASTR + akq + 2] = l;
                split_bf16(pv0.w, h, l); sAhi[ar0 * ASTR + akq + 3] = h; sAlo[ar0 * ASTR + akq + 3] = l;
                split_bf16(pv1.x, h, l); sAhi[(ar0 + 32) * ASTR + akq + 0] = h; sAlo[(ar0 + 32) * ASTR + akq + 0] = l;
                split_bf16(pv1.y, h, l); sAhi[(ar0 + 32) * ASTR + akq + 1] = h; sAlo[(ar0 + 32) * ASTR + akq + 1] = l;
                split_bf16(pv1.z, h, l); sAhi[(ar0 + 32) * ASTR + akq + 2] = h; sAlo[(ar0 + 32) * ASTR + akq + 2] = l;
                split_bf16(pv1.w, h, l); sAhi[(ar0 + 32) * ASTR + akq + 3] = h; sAlo[(ar0 + 32) * ASTR + akq + 3] = l;
            }
            __syncthreads();

            if (kt < 31) {
                int k0 = (kt + 1) << 5;
                pv0 = *reinterpret_cast<const float4*>(hsrc + (size_t)ar0 * 1024 + k0 + akq);
                pv1 = *reinterpret_cast<const float4*>(hsrc + (size_t)(ar0 + 32) * 1024 + k0 + akq);
            }

            const int kb = kt << 5;
            #pragma unroll
            for (int kk = 0; kk < 32; kk += 16) {
                uint32_t Ah[4], Al[4];
                Ah[0] = ld_pair(&sAhi[(m0w + g) * ASTR + kk + 2 * tig]);
                Ah[1] = ld_pair(&sAhi[(m0w + g + 8) * ASTR + kk + 2 * tig]);
                Ah[2] = ld_pair(&sAhi[(m0w + g) * ASTR + kk + 2 * tig + 8]);
                Ah[3] = ld_pair(&sAhi[(m0w + g + 8) * ASTR + kk + 2 * tig + 8]);
                Al[0] = ld_pair(&sAlo[(m0w + g) * ASTR + kk + 2 * tig]);
                Al[1] = ld_pair(&sAlo[(m0w + g + 8) * ASTR + kk + 2 * tig]);
                Al[2] = ld_pair(&sAlo[(m0w + g) * ASTR + kk + 2 * tig + 8]);
                Al[3] = ld_pair(&sAlo[(m0w + g + 8) * ASTR + kk + 2 * tig + 8]);
                #pragma unroll
                for (int nt = 0; nt < 3; nt++) {
                    int r0 = n0w + 8 * nt + g;
                    uint32_t Bh[2], Bl[2];
                    Bh[0] = ld_pair(&sWhi[r0 * WSTR + kb + kk + 2 * tig]);
                    Bh[1] = ld_pair(&sWhi[r0 * WSTR + kb + kk + 2 * tig + 8]);
                    Bl[0] = ld_pair(&sWlo[r0 * WSTR + kb + kk + 2 * tig]);
                    Bl[1] = ld_pair(&sWlo[r0 * WSTR + kb + kk + 2 * tig + 8]);
                    mma16816(acc[nt], Ah, Bh);
                    mma16816(acc[nt], Ah, Bl);
                    mma16816(acc[nt], Al, Bh);
                }
            }
            // single sync per tile (double-buffered)
        }

        __syncthreads();   // all MMAs done before shg aliases the A buffers
        #pragma unroll
        for (int nt = 0; nt < 3; nt++) {
            int col = n0w + 8 * nt + 2 * tig;
            shg[(m0w + g) * 49 + col]         = acc[nt][0];
            shg[(m0w + g) * 49 + col + 1]     = acc[nt][1];
            shg[(m0w + g + 8) * 49 + col]     = acc[nt][2];
            shg[(m0w + g + 8) * 49 + col + 1] = acc[nt][3];
        }
        __syncthreads();

        // fused gates: 4 units per thread
        {
            const float* xrp = reinterpret_cast<const float*>(&xr4);
            const float* xzp = reinterpret_cast<const float*>(&xz4);
            const float* xnp = reinterpret_cast<const float*>(&xn4);
            const float* hop = reinterpret_cast<const float*>(&ho4);
            float4 res;
            float* rp = reinterpret_cast<float*>(&res);
            #pragma unroll
            for (int i = 0; i < 4; i++) {
                int uu = uu0 + i;
                float hr = shg[b_ * 49 + uu] + sbh[uu];
                float hz = shg[b_ * 49 + 16 + uu] + sbh[16 + uu];
                float hn = shg[b_ * 49 + 32 + uu] + sbh[32 + uu];
                float r = 1.f / (1.f + expf(-(xrp[i] + hr)));
                float z = 1.f / (1.f + expf(-(xzp[i] + hz)));
                float n = tanhf(xnp[i] + r * hn);
                rp[i] = (1.f - z) * n + z * hop[i];
            }
            *reinterpret_cast<float4*>(hdst + (size_t)b_ * 1024 + j0 + uu0) = res;
        }

        gridbar64();
    }
}

// =====================================================================
// launch
// =====================================================================
extern "C" void kernel_launch(void* const* d_in, const int* in_sizes, int n_in,
                              void* d_out, int out_size)
{
    const float* inp    = (const float*)d_in[0];  // (64,256,1024)
    const float* hidden = (const float*)d_in[1];  // (1,64,1024)
    const float* W_in   = (const float*)d_in[2];  // (1024,1024)
    const float* b_in   = (const float*)d_in[3];  // (1024)
    const float* W_ih   = (const float*)d_in[4];  // (3072,1024)
    const float* b_ih   = (const float*)d_in[5];  // (3072)
    const float* W_hh   = (const float*)d_in[6];  // (3072,1024)
    const float* b_hh   = (const float*)d_in[7];  // (3072)
    const float* W_out  = (const float*)d_in[8];  // (1024,1024)
    const float* b_out  = (const float*)d_in[9];  // (1024)
    float* out = (float*)d_out;

    float* xg    = g_xg;
    float* wt    = g_wt;
    float* wcomb = g_wcomb;
    float* bcomb = g_bcomb;
    float* hbuf  = g_h;

    cudaFuncSetAttribute(gemm3x_k, cudaFuncAttributeMaxDynamicSharedMemorySize, GEMM_SMEM);
    cudaFuncSetAttribute(gru_persist_k, cudaFuncAttributeMaxDynamicSharedMemorySize, GRU_SMEM);

    // W_in^T
    transpose_k<<<dim3(32, 32), dim3(32, 8)>>>(W_in, wt);
    // b_comb
    bcomb_k<<<12, 256>>>(W_ih, b_in, b_ih, bcomb);
    // W_comb = W_ih @ W_in  (M=3072, N=1024, K=1024)
    gemm3x_k<<<dim3(8, 24), 256, GEMM_SMEM>>>(W_ih, wt, nullptr, wcomb, 3072, 1024, 1024);
    // x_gates = inp @ W_comb^T + b_comb  (M=16384, N=3072, K=1024)
    gemm3x_k<<<dim3(24, 128), 256, GEMM_SMEM>>>(inp, wcomb, bcomb, xg, 16384, 3072, 1024);
    // full recurrence in ONE persistent kernel (final h lands in hbuf[0])
    gru_persist_k<<<NBLK, 256, GRU_SMEM>>>(xg, W_hh, b_hh, hidden, hbuf);
    // out_last = h_T @ W_out^T + b_out  (M=64, N=1024, K=1024)
    gemm3x_k<<<dim3(8, 1), 256, GEMM_SMEM>>>(hbuf, W_out, b_out, out, 64, 1024, 1024);
    // hidden_out = h_T
    copy_k<<<256, 256>>>(hbuf, out + 65536, 65536);
}

// round 5
// speedup vs baseline: 1.2490x; 1.0550x over previous
#include <cuda_runtime.h>
#include <cuda_bf16.h>
#include <cstdint>
#include <math.h>

// ---------------- static device scratch (no cudaMalloc allowed) ----------------
__device__ float g_xg[16384ull * 3072];   // (B*T, 3H) gate pre-activations, row = b*256+t
__device__ float g_wt[1024 * 1024];       // W_in transposed: [d][h]
__device__ float g_wcomb[3072 * 1024];    // W_ih @ W_in : [g][d]
__device__ float g_bcomb[3072];           // W_ih @ b_in + b_ih
__device__ float g_h[2 * 64 * 1024];      // ping-pong hidden state
__device__ unsigned g_cnt = 0;            // grid barrier arrive counter
__device__ unsigned g_gen = 0;            // grid barrier generation

// ---------------- helpers ----------------
__device__ __forceinline__ void split_bf16(float x, __nv_bfloat16& hi, __nv_bfloat16& lo) {
    hi = __float2bfloat16(x);
    lo = __float2bfloat16(x - __bfloat162float(hi));
}

__device__ __forceinline__ uint32_t ld_pair(const __nv_bfloat16* p) {
    return *reinterpret_cast<const uint32_t*>(p);
}

__device__ __forceinline__ void mma16816(float* c, const uint32_t* a, const uint32_t* b) {
    asm volatile(
        "mma.sync.aligned.m16n8k16.row.col.f32.bf16.bf16.f32 "
        "{%0,%1,%2,%3}, {%4,%5,%6,%7}, {%8,%9}, {%0,%1,%2,%3};\n"
        : "+f"(c[0]), "+f"(c[1]), "+f"(c[2]), "+f"(c[3])
        : "r"(a[0]), "r"(a[1]), "r"(a[2]), "r"(a[3]), "r"(b[0]), "r"(b[1]));
}

// =====================================================================
// Transpose 1024x1024: out[d][h] = in[h][d]
// =====================================================================
__global__ void transpose_k(const float* __restrict__ in, float* __restrict__ out) {
    __shared__ float t[32][33];
    int x = blockIdx.x * 32 + threadIdx.x;
    int y = blockIdx.y * 32 + threadIdx.y;
    #pragma unroll
    for (int i = 0; i < 32; i += 8)
        t[threadIdx.y + i][threadIdx.x] = in[(size_t)(y + i) * 1024 + x];
    __syncthreads();
    int xo = blockIdx.y * 32 + threadIdx.x;
    int yo = blockIdx.x * 32 + threadIdx.y;
    #pragma unroll
    for (int i = 0; i < 32; i += 8)
        out[(size_t)(yo + i) * 1024 + xo] = t[threadIdx.x][threadIdx.y + i];
}

// =====================================================================
// b_comb[g] = b_ih[g] + sum_h W_ih[g,h] * b_in[h]
// =====================================================================
__global__ void bcomb_k(const float* __restrict__ W_ih, const float* __restrict__ b_in,
                        const float* __restrict__ b_ih, float* __restrict__ out) {
    int g = blockIdx.x * blockDim.x + threadIdx.x;
    if (g < 3072) {
        float s = b_ih[g];
        const float* row = W_ih + (size_t)g * 1024;
        for (int h = 0; h < 1024; h++) s += row[h] * b_in[h];
        out[g] = s;
    }
}

__global__ void copy_k(const float* __restrict__ s, float* __restrict__ d, int n) {
    int i = blockIdx.x * blockDim.x + threadIdx.x;
    if (i < n) d[i] = s[i];
}

// =====================================================================
// Generic NT GEMM: C[M,N] = A[M,K] @ B[N,K]^T (+ bias[N])
// bf16 hi/lo 3-product split, fp32 accumulate.
// Block tile 128x128, BK=32, 256 threads = 8 warps (4 m-warps x 2 n-warps).
// Dynamic smem, DOUBLE-BUFFERED, register prefetch, 1 sync per k-tile.
// (At HBM roofline per ncu R4 — left unchanged this round.)
// =====================================================================
#define GTILE 5120   // 128*40 elems per array
#define GEMM_SMEM (2 * 4 * GTILE * 2)   // bytes = 81920

__global__ __launch_bounds__(256, 1)
void gemm3x_k(const float* __restrict__ A, const float* __restrict__ B,
              const float* __restrict__ bias, float* __restrict__ C,
              int M, int N, int K)
{
    extern __shared__ __nv_bfloat16 gsm[];

    const int tid = threadIdx.x;
    const int lane = tid & 31;
    const int warp = tid >> 5;
    const int g = lane >> 2;      // group id 0..7
    const int tig = lane & 3;     // thread in group
    const int m0w = (warp >> 1) * 32;
    const int n0w = (warp & 1) * 64;

    const int mBase = blockIdx.y * 128;
    const int nBase = blockIdx.x * 128;

    float acc[2][8][4];
    #pragma unroll
    for (int mt = 0; mt < 2; mt++)
        #pragma unroll
        for (int nt = 0; nt < 8; nt++)
            #pragma unroll
            for (int i = 0; i < 4; i++) acc[mt][nt][i] = 0.f;

    const int nKT = K >> 5;
    float4 pa[4], pb[4];

    // prologue: prefetch tile 0 into regs
    #pragma unroll
    for (int it = 0; it < 4; it++) {
        int id = tid + it * 256;
        int r = id >> 3;
        int kq = (id & 7) << 2;
        int gr = mBase + r;
        pa[it] = (gr < M) ? *reinterpret_cast<const float4*>(A + (size_t)gr * K + kq)
                          : make_float4(0.f, 0.f, 0.f, 0.f);
        pb[it] = *reinterpret_cast<const float4*>(B + (size_t)(nBase + r) * K + kq);
    }

    for (int kt = 0; kt < nKT; kt++) {
        __nv_bfloat16* base = gsm + (size_t)(kt & 1) * (4 * GTILE);
        __nv_bfloat16* sAhi = base;
        __nv_bfloat16* sAlo = base + GTILE;
        __nv_bfloat16* sBhi = base + 2 * GTILE;
        __nv_bfloat16* sBlo = base + 3 * GTILE;

        // store prefetched regs -> smem (split)
        #pragma unroll
        for (int it = 0; it < 4; it++) {
            int id = tid + it * 256;
            int r = id >> 3;
            int kq = (id & 7) << 2;
            __nv_bfloat16 h, l;
            split_bf16(pa[it].x, h, l); sAhi[r * 40 + kq + 0] = h; sAlo[r * 40 + kq + 0] = l;
            split_bf16(pa[it].y, h, l); sAhi[r * 40 + kq + 1] = h; sAlo[r * 40 + kq + 1] = l;
            split_bf16(pa[it].z, h, l); sAhi[r * 40 + kq + 2] = h; sAlo[r * 40 + kq + 2] = l;
            split_bf16(pa[it].w, h, l); sAhi[r * 40 + kq + 3] = h; sAlo[r * 40 + kq + 3] = l;
            split_bf16(pb[it].x, h, l); sBhi[r * 40 + kq + 0] = h; sBlo[r * 40 + kq + 0] = l;
            split_bf16(pb[it].y, h, l); sBhi[r * 40 + kq + 1] = h; sBlo[r * 40 + kq + 1] = l;
            split_bf16(pb[it].z, h, l); sBhi[r * 40 + kq + 2] = h; sBlo[r * 40 + kq + 2] = l;
            split_bf16(pb[it].w, h, l); sBhi[r * 40 + kq + 3] = h; sBlo[r * 40 + kq + 3] = l;
        }
        __syncthreads();

        // prefetch next tile under this tile's MMAs
        if (kt + 1 < nKT) {
            int k0 = (kt + 1) << 5;
            #pragma unroll
            for (int it = 0; it < 4; it++) {
                int id = tid + it * 256;
                int r = id >> 3;
                int kq = (id & 7) << 2;
                int gr = mBase + r;
                pa[it] = (gr < M) ? *reinterpret_cast<const float4*>(A + (size_t)gr * K + k0 + kq)
                                  : make_float4(0.f, 0.f, 0.f, 0.f);
                pb[it] = *reinterpret_cast<const float4*>(B + (size_t)(nBase + r) * K + k0 + kq);
            }
        }

        #pragma unroll
        for (int kk = 0; kk < 32; kk += 16) {
            uint32_t Ah[2][4], Al[2][4], Bh[8][2], Bl[8][2];
            #pragma unroll
            for (int mt = 0; mt < 2; mt++) {
                int r0 = m0w + 16 * mt;
                Ah[mt][0] = ld_pair(&sAhi[(r0 + g) * 40 + kk + 2 * tig]);
                Ah[mt][1] = ld_pair(&sAhi[(r0 + g + 8) * 40 + kk + 2 * tig]);
                Ah[mt][2] = ld_pair(&sAhi[(r0 + g) * 40 + kk + 2 * tig + 8]);
                Ah[mt][3] = ld_pair(&sAhi[(r0 + g + 8) * 40 + kk + 2 * tig + 8]);
                Al[mt][0] = ld_pair(&sAlo[(r0 + g) * 40 + kk + 2 * tig]);
                Al[mt][1] = ld_pair(&sAlo[(r0 + g + 8) * 40 + kk + 2 * tig]);
                Al[mt][2] = ld_pair(&sAlo[(r0 + g) * 40 + kk + 2 * tig + 8]);
                Al[mt][3] = ld_pair(&sAlo[(r0 + g + 8) * 40 + kk + 2 * tig + 8]);
            }
            #pragma unroll
            for (int nt = 0; nt < 8; nt++) {
                int r0 = n0w + 8 * nt + g;
                Bh[nt][0] = ld_pair(&sBhi[r0 * 40 + kk + 2 * tig]);
                Bh[nt][1] = ld_pair(&sBhi[r0 * 40 + kk + 2 * tig + 8]);
                Bl[nt][0] = ld_pair(&sBlo[r0 * 40 + kk + 2 * tig]);
                Bl[nt][1] = ld_pair(&sBlo[r0 * 40 + kk + 2 * tig + 8]);
            }
            #pragma unroll
            for (int mt = 0; mt < 2; mt++)
                #pragma unroll
                for (int nt = 0; nt < 8; nt++) {
                    mma16816(acc[mt][nt], Ah[mt], Bh[nt]);
                    mma16816(acc[mt][nt], Ah[mt], Bl[nt]);
                    mma16816(acc[mt][nt], Al[mt], Bh[nt]);
                }
        }
        // no trailing sync: next iter writes the OTHER buffer, whose readers
        // all passed this iter's __syncthreads before issuing those reads.
    }

    // epilogue
    #pragma unroll
    for (int mt = 0; mt < 2; mt++) {
        #pragma unroll
        for (int nt = 0; nt < 8; nt++) {
            int col = nBase + n0w + 8 * nt + 2 * tig;
            float b0 = bias ? bias[col] : 0.f;
            float b1 = bias ? bias[col + 1] : 0.f;
            int r0 = mBase + m0w + 16 * mt + g;
            if (r0 < M) {
                C[(size_t)r0 * N + col]     = acc[mt][nt][0] + b0;
                C[(size_t)r0 * N + col + 1] = acc[mt][nt][1] + b1;
            }
            if (r0 + 8 < M) {
                C[(size_t)(r0 + 8) * N + col]     = acc[mt][nt][2] + b0;
                C[(size_t)(r0 + 8) * N + col + 1] = acc[mt][nt][3] + b1;
            }
        }
    }
}

// =====================================================================
// Persistent GRU recurrence kernel.
// grid = 64 blocks x 256 threads, ALL co-resident (1 CTA/SM).
// CHANGE (R5): 18 independent accumulator chains per warp —
// acc[kk-parity][split-product][nt] — chain depth per step drops 192 -> 32.
// =====================================================================
#define WSTR 1032                       // W smem row stride (bank conflict-free)
#define ASTR 40                         // A smem row stride
#define GRU_SMEM ((2 * 48 * WSTR + 2 * 2 * 64 * ASTR) * 2)   // 218624 bytes
#define NBLK 64

__device__ __forceinline__ void gridbar64() {
    __syncthreads();
    if (threadIdx.x == 0) {
        __threadfence();                       // release (cumulative): publish block's h writes
        unsigned gen = atomicAdd(&g_gen, 0u);  // read generation BEFORE arriving
        if (atomicAdd(&g_cnt, 1u) == NBLK - 1u) {
            atomicExch(&g_cnt, 0u);
            __threadfence();
            atomicAdd(&g_gen, 1u);
        } else {
            while (atomicAdd(&g_gen, 0u) == gen) { }
        }
        __threadfence();                       // acquire
    }
    __syncthreads();
}

__global__ __launch_bounds__(256, 1)
void gru_persist_k(const float* __restrict__ xg, const float* __restrict__ W_hh,
                   const float* __restrict__ b_hh, const float* __restrict__ hidden,
                   float* __restrict__ hbuf)
{
    extern __shared__ __nv_bfloat16 dsm[];
    __nv_bfloat16* sWhi = dsm;                       // [48][WSTR]
    __nv_bfloat16* sWlo = dsm + 48 * WSTR;
    __nv_bfloat16* sAb  = dsm + 2 * 48 * WSTR;       // [2 buf][hi|lo][64][ASTR]
    float* shg = reinterpret_cast<float*>(sAb);      // [64][49] (reuses A buffers)
    __shared__ float sbh[48];

    const int tid = threadIdx.x;
    const int lane = tid & 31;
    const int warp = tid >> 5;
    const int g = lane >> 2;
    const int tig = lane & 3;
    const int m0w = (warp >> 1) * 16;   // 4 m-warps (batch rows)
    const int n0w = (warp & 1) * 24;    // 2 n-warps, 3 n8-tiles each
    const int j0 = blockIdx.x * 16;

    // ---- stage W_hh slice (48 rows x 1024) into smem, hi/lo ----
    for (int idx = tid; idx < 48 * 256; idx += 256) {
        int r = idx >> 8;                 // 0..47
        int c4 = (idx & 255) << 2;        // 0..1020
        int grow = (r >> 4) * 1024 + j0 + (r & 15);
        float4 v = *reinterpret_cast<const float4*>(W_hh + (size_t)grow * 1024 + c4);
        __nv_bfloat16 h, l;
        split_bf16(v.x, h, l); sWhi[r * WSTR + c4 + 0] = h; sWlo[r * WSTR + c4 + 0] = l;
        split_bf16(v.y, h, l); sWhi[r * WSTR + c4 + 1] = h; sWlo[r * WSTR + c4 + 1] = l;
        split_bf16(v.z, h, l); sWhi[r * WSTR + c4 + 2] = h; sWlo[r * WSTR + c4 + 2] = l;
        split_bf16(v.w, h, l); sWhi[r * WSTR + c4 + 3] = h; sWlo[r * WSTR + c4 + 3] = l;
    }
    if (tid < 48) sbh[tid] = b_hh[(tid >> 4) * 1024 + j0 + (tid & 15)];
    __syncthreads();

    const int b_  = tid >> 2;             // epilogue: batch row
    const int uu0 = (tid & 3) << 2;       // epilogue: first of 4 units
    const int ar0 = tid >> 3;             // staging row (0..31), +32 for 2nd
    const int akq = (tid & 7) << 2;       // staging col quad

    for (int t = 0; t < 256; t++) {
        const float* hsrc = (t == 0) ? hidden : (hbuf + (size_t)(t & 1) * 65536);
        float* hdst = hbuf + (size_t)((t + 1) & 1) * 65536;

        // prefetch epilogue operands (independent of MMA chain)
        const float* xrow = xg + (size_t)(b_ * 256 + t) * 3072 + j0 + uu0;
        float4 xr4 = *reinterpret_cast<const float4*>(xrow);
        float4 xz4 = *reinterpret_cast<const float4*>(xrow + 1024);
        float4 xn4 = *reinterpret_cast<const float4*>(xrow + 2048);
        float4 ho4 = *reinterpret_cast<const float4*>(hsrc + (size_t)b_ * 1024 + j0 + uu0);

        // 18 INDEPENDENT accumulator chains: [kk-parity][split][nt][4]
        float acc[2][3][3][4];
        #pragma unroll
        for (int ki = 0; ki < 2; ki++)
            #pragma unroll
            for (int s = 0; s < 3; s++)
                #pragma unroll
                for (int nt = 0; nt < 3; nt++)
                    #pragma unroll
                    for (int i = 0; i < 4; i++) acc[ki][s][nt][i] = 0.f;

        // prologue: prefetch h tile 0
        float4 pv0 = *reinterpret_cast<const float4*>(hsrc + (size_t)ar0 * 1024 + akq);
        float4 pv1 = *reinterpret_cast<const float4*>(hsrc + (size_t)(ar0 + 32) * 1024 + akq);

        for (int kt = 0; kt < 32; kt++) {
            __nv_bfloat16* sAhi = sAb + (size_t)(kt & 1) * (2 * 64 * ASTR);
            __nv_bfloat16* sAlo = sAhi + 64 * ASTR;

            {
                __nv_bfloat16 h, l;
                split_bf16(pv0.x, h, l); sAhi[ar0 * ASTR + akq + 0] = h; sAlo[ar0 * ASTR + akq + 0] = l;
                split_bf16(pv0.y, h, l); sAhi[ar0 * ASTR + akq + 1] = h; sAlo[ar0 * ASTR + akq + 1] = l;
                split_bf16(pv0.z, h, l); sAhi[ar0 * ASTR + akq + 2] = h; sAlo[ar0 * ASTR + akq + 2] = l;
                split_bf16(pv0.w, h, l); sAhi[ar0 * ASTR + akq + 3] = h; sAlo[ar0 * ASTR + akq + 3] = l;
                split_bf16(pv1.x, h, l); sAhi[(ar0 + 32) * ASTR + akq + 0] = h; sAlo[(ar0 + 32) * ASTR + akq + 0] = l;
                split_bf16(pv1.y, h, l); sAhi[(ar0 + 32) * ASTR + akq + 1] = h; sAlo[(ar0 + 32) * ASTR + akq + 1] = l;
                split_bf16(pv1.z, h, l); sAhi[(ar0 + 32) * ASTR + akq + 2] = h; sAlo[(ar0 + 32) * ASTR + akq + 2] = l;
                split_bf16(pv1.w, h, l); sAhi[(ar0 + 32) * ASTR + akq + 3] = h; sAlo[(ar0 + 32) * ASTR + akq + 3] = l;
            }
            __syncthreads();

            if (kt < 31) {
                int k0 = (kt + 1) << 5;
                pv0 = *reinterpret_cast<const float4*>(hsrc + (size_t)ar0 * 1024 + k0 + akq);
                pv1 = *reinterpret_cast<const float4*>(hsrc + (size_t)(ar0 + 32) * 1024 + k0 + akq);
            }

            const int kb = kt << 5;
            #pragma unroll
            for (int ki = 0; ki < 2; ki++) {
                const int kk = ki << 4;
                uint32_t Ah[4], Al[4];
                Ah[0] = ld_pair(&sAhi[(m0w + g) * ASTR + kk + 2 * tig]);
                Ah[1] = ld_pair(&sAhi[(m0w + g + 8) * ASTR + kk + 2 * tig]);
                Ah[2] = ld_pair(&sAhi[(m0w + g) * ASTR + kk + 2 * tig + 8]);
                Ah[3] = ld_pair(&sAhi[(m0w + g + 8) * ASTR + kk + 2 * tig + 8]);
                Al[0] = ld_pair(&sAlo[(m0w + g) * ASTR + kk + 2 * tig]);
                Al[1] = ld_pair(&sAlo[(m0w + g + 8) * ASTR + kk + 2 * tig]);
                Al[2] = ld_pair(&sAlo[(m0w + g) * ASTR + kk + 2 * tig + 8]);
                Al[3] = ld_pair(&sAlo[(m0w + g + 8) * ASTR + kk + 2 * tig + 8]);
                #pragma unroll
                for (int nt = 0; nt < 3; nt++) {
                    int r0 = n0w + 8 * nt + g;
                    uint32_t Bh[2], Bl[2];
                    Bh[0] = ld_pair(&sWhi[r0 * WSTR + kb + kk + 2 * tig]);
                    Bh[1] = ld_pair(&sWhi[r0 * WSTR + kb + kk + 2 * tig + 8]);
                    Bl[0] = ld_pair(&sWlo[r0 * WSTR + kb + kk + 2 * tig]);
                    Bl[1] = ld_pair(&sWlo[r0 * WSTR + kb + kk + 2 * tig + 8]);
                    mma16816(acc[ki][0][nt], Ah, Bh);   // independent chains:
                    mma16816(acc[ki][1][nt], Ah, Bl);   // each (ki, split, nt)
                    mma16816(acc[ki][2][nt], Al, Bh);   // has its own accumulator
                }
            }
            // single sync per tile (double-buffered)
        }

        __syncthreads();   // all MMAs done before shg aliases the A buffers

        // reduce 6 partial sets per nt, then write hg tile to smem
        #pragma unroll
        for (int nt = 0; nt < 3; nt++) {
            float red[4];
            #pragma unroll
            for (int i = 0; i < 4; i++)
                red[i] = ((acc[0][0][nt][i] + acc[0][1][nt][i]) + (acc[0][2][nt][i] + acc[1][0][nt][i]))
                       + (acc[1][1][nt][i] + acc[1][2][nt][i]);
            int col = n0w + 8 * nt + 2 * tig;
            shg[(m0w + g) * 49 + col]         = red[0];
            shg[(m0w + g) * 49 + col + 1]     = red[1];
            shg[(m0w + g + 8) * 49 + col]     = red[2];
            shg[(m0w + g + 8) * 49 + col + 1] = red[3];
        }
        __syncthreads();

        // fused gates: 4 units per thread
        {
            const float* xrp = reinterpret_cast<const float*>(&xr4);
            const float* xzp = reinterpret_cast<const float*>(&xz4);
            const float* xnp = reinterpret_cast<const float*>(&xn4);
            const float* hop = reinterpret_cast<const float*>(&ho4);
            float4 res;
            float* rp = reinterpret_cast<float*>(&res);
            #pragma unroll
            for (int i = 0; i < 4; i++) {
                int uu = uu0 + i;
                float hr = shg[b_ * 49 + uu] + sbh[uu];
                float hz = shg[b_ * 49 + 16 + uu] + sbh[16 + uu];
                float hn = shg[b_ * 49 + 32 + uu] + sbh[32 + uu];
                float r = 1.f / (1.f + expf(-(xrp[i] + hr)));
                float z = 1.f / (1.f + expf(-(xzp[i] + hz)));
                float n = tanhf(xnp[i] + r * hn);
                rp[i] = (1.f - z) * n + z * hop[i];
            }
            *reinterpret_cast<float4*>(hdst + (size_t)b_ * 1024 + j0 + uu0) = res;
        }

        gridbar64();
    }
}

// =====================================================================
// launch
// =====================================================================
extern "C" void kernel_launch(void* const* d_in, const int* in_sizes, int n_in,
                              void* d_out, int out_size)
{
    const float* inp    = (const float*)d_in[0];  // (64,256,1024)
    const float* hidden = (const float*)d_in[1];  // (1,64,1024)
    const float* W_in   = (const float*)d_in[2];  // (1024,1024)
    const float* b_in   = (const float*)d_in[3];  // (1024)
    const float* W_ih   = (const float*)d_in[4];  // (3072,1024)
    const float* b_ih   = (const float*)d_in[5];  // (3072)
    const float* W_hh   = (const float*)d_in[6];  // (3072,1024)
    const float* b_hh   = (const float*)d_in[7];  // (3072)
    const float* W_out  = (const float*)d_in[8];  // (1024,1024)
    const float* b_out  = (const float*)d_in[9];  // (1024)
    float* out = (float*)d_out;

    float* xg    = g_xg;
    float* wt    = g_wt;
    float* wcomb = g_wcomb;
    float* bcomb = g_bcomb;
    float* hbuf  = g_h;

    cudaFuncSetAttribute(gemm3x_k, cudaFuncAttributeMaxDynamicSharedMemorySize, GEMM_SMEM);
    cudaFuncSetAttribute(gru_persist_k, cudaFuncAttributeMaxDynamicSharedMemorySize, GRU_SMEM);

    // W_in^T
    transpose_k<<<dim3(32, 32), dim3(32, 8)>>>(W_in, wt);
    // b_comb
    bcomb_k<<<12, 256>>>(W_ih, b_in, b_ih, bcomb);
    // W_comb = W_ih @ W_in  (M=3072, N=1024, K=1024)
    gemm3x_k<<<dim3(8, 24), 256, GEMM_SMEM>>>(W_ih, wt, nullptr, wcomb, 3072, 1024, 1024);
    // x_gates = inp @ W_comb^T + b_comb  (M=16384, N=3072, K=1024)
    gemm3x_k<<<dim3(24, 128), 256, GEMM_SMEM>>>(inp, wcomb, bcomb, xg, 16384, 3072, 1024);
    // full recurrence in ONE persistent kernel (final h lands in hbuf[0])
    gru_persist_k<<<NBLK, 256, GRU_SMEM>>>(xg, W_hh, b_hh, hidden, hbuf);
    // out_last = h_T @ W_out^T + b_out  (M=64, N=1024, K=1024)
    gemm3x_k<<<dim3(8, 1), 256, GEMM_SMEM>>>(hbuf, W_out, b_out, out, 64, 1024, 1024);
    // hidden_out = h_T
    copy_k<<<256, 256>>>(hbuf, out + 65536, 65536);
}